// round 4
// baseline (speedup 1.0000x reference)
#include <cuda_runtime.h>
#include <math.h>

#define NTOK   16384
#define EDIM   64
#define NH     8
#define HE     512
#define QKVDIM 1536
#define NITER  16

typedef unsigned long long ull;

// Scratch (static device memory — allocation-free)
__device__ float g_qkv[NTOK * QKVDIM];   // per token: q[0:512) (pre-scaled), k[512:1024), v[1024:1536)
__device__ float g_res[NTOK * HE];       // per token: res[h*64+i]

// ---------------- f32x2 packed-math helpers (Blackwell FFMA2 path) ----------
__device__ __forceinline__ ull pack2(float lo, float hi) {
    ull r; asm("mov.b64 %0, {%1, %2};" : "=l"(r) : "f"(lo), "f"(hi)); return r;
}
__device__ __forceinline__ ull dup2(float v) { return pack2(v, v); }
__device__ __forceinline__ float lo2(ull v) {
    float f; asm("{ .reg .b32 hi; mov.b64 {%0, hi}, %1; }" : "=f"(f) : "l"(v)); return f;
}
__device__ __forceinline__ float hi2(ull v) {
    float f; asm("{ .reg .b32 lo; mov.b64 {lo, %0}, %1; }" : "=f"(f) : "l"(v)); return f;
}
__device__ __forceinline__ void ffma2(ull& d, ull a, ull b) {
    asm("fma.rn.f32x2 %0, %1, %2, %0;" : "+l"(d) : "l"(a), "l"(b));
}
__device__ __forceinline__ ull add2(ull a, ull b) {
    ull r; asm("add.rn.f32x2 %0, %1, %2;" : "=l"(r) : "l"(a), "l"(b)); return r;
}
__device__ __forceinline__ ull mul2(ull a, ull b) {
    ull r; asm("mul.rn.f32x2 %0, %1, %2;" : "=l"(r) : "l"(a), "l"(b)); return r;
}
__device__ __forceinline__ float hsum2(ull v) { return lo2(v) + hi2(v); }
// relu(x + nt) on both packed halves: 1 add.f32x2 + 2 scalar max on the halves
__device__ __forceinline__ ull relu2_add(ull x2, ull nt2) {
    ull r;
    asm("{\n\t"
        ".reg .f32 lo, hi;\n\t"
        "add.rn.f32x2 %0, %1, %2;\n\t"
        "mov.b64 {lo, hi}, %0;\n\t"
        "max.f32 lo, lo, 0f00000000;\n\t"
        "max.f32 hi, hi, 0f00000000;\n\t"
        "mov.b64 %0, {lo, hi};\n\t"
        "}" : "=l"(r) : "l"(x2), "l"(nt2));
    return r;
}

// ---------------------------------------------------------------------------
// K1: fused QKV projection.  y[n,o] = sum_k x[n,k]*W[o,k] + b[o]
// Tile: M=128 x N=128, K=64 in 2 chunks of 32. 8 rows x 4 col-pairs (FFMA2).
// ---------------------------------------------------------------------------
__global__ __launch_bounds__(256, 2) void k_qkv(
    const float* __restrict__ x,
    const float* __restrict__ Wq, const float* __restrict__ bq,
    const float* __restrict__ Wk, const float* __restrict__ bk,
    const float* __restrict__ Wv, const float* __restrict__ bv,
    const float* __restrict__ alpha_p)
{
    __shared__ float aT[32][132];   // aT[k][m]
    __shared__ float bT[32][132];   // bT[k][o]
    const int tid   = threadIdx.x;
    const int bm    = blockIdx.x;           // 0..127
    const int oBase = blockIdx.y * 128;     // 0..1408 step 128

    const float* W; const float* bias;
    if (oBase < 512)       { W = Wq; bias = bq; }
    else if (oBase < 1024) { W = Wk; bias = bk; }
    else                   { W = Wv; bias = bv; }
    const int wBase = oBase & 511;

    const int r0 = (tid >> 4) * 8;   // 0..120
    const int c0 = (tid & 15) * 8;   // 0..120

    ull acc2[8][4];                  // [row][col-pair]
    #pragma unroll
    for (int r = 0; r < 8; r++)
        #pragma unroll
        for (int c = 0; c < 4; c++) acc2[r][c] = 0ULL;

    #pragma unroll
    for (int kc = 0; kc < 2; kc++) {
        __syncthreads();
        {   // A chunk: 128 rows x 32 k
            int f = tid;
            #pragma unroll
            for (int rep = 0; rep < 4; rep++, f += 256) {
                int row = f >> 3;
                int c4  = f & 7;
                float4 v = *(const float4*)(x + (size_t)(bm * 128 + row) * 64 + kc * 32 + c4 * 4);
                aT[c4 * 4 + 0][row] = v.x;
                aT[c4 * 4 + 1][row] = v.y;
                aT[c4 * 4 + 2][row] = v.z;
                aT[c4 * 4 + 3][row] = v.w;
            }
        }
        {   // B chunk: 128 outputs x 32 k
            int f = tid;
            #pragma unroll
            for (int rep = 0; rep < 4; rep++, f += 256) {
                int o  = f >> 3;
                int c4 = f & 7;
                float4 v = *(const float4*)(W + (size_t)(wBase + o) * 64 + kc * 32 + c4 * 4);
                bT[c4 * 4 + 0][o] = v.x;
                bT[c4 * 4 + 1][o] = v.y;
                bT[c4 * 4 + 2][o] = v.z;
                bT[c4 * 4 + 3][o] = v.w;
            }
        }
        __syncthreads();

        #pragma unroll 8
        for (int k = 0; k < 32; k++) {
            float4 a0 = *(const float4*)&aT[k][r0];
            float4 a1 = *(const float4*)&aT[k][r0 + 4];
            float4 b0 = *(const float4*)&bT[k][c0];
            float4 b1 = *(const float4*)&bT[k][c0 + 4];
            ull bp[4] = {pack2(b0.x, b0.y), pack2(b0.z, b0.w),
                         pack2(b1.x, b1.y), pack2(b1.z, b1.w)};
            float a[8] = {a0.x, a0.y, a0.z, a0.w, a1.x, a1.y, a1.z, a1.w};
            #pragma unroll
            for (int r = 0; r < 8; r++) {
                ull ad = dup2(a[r]);
                #pragma unroll
                for (int c = 0; c < 4; c++) ffma2(acc2[r][c], ad, bp[c]);
            }
        }
    }

    const float am1   = alpha_p[0] - 1.f;
    const float scale = (oBase < 512) ? am1 * 0.125f : 1.f;
    const ull   sc2   = dup2(scale);

    ull bb2[4];
    #pragma unroll
    for (int c = 0; c < 4; c++)
        bb2[c] = pack2(bias[wBase + c0 + 2 * c], bias[wBase + c0 + 2 * c + 1]);

    #pragma unroll
    for (int r = 0; r < 8; r++) {
        float* dst = g_qkv + (size_t)(bm * 128 + r0 + r) * QKVDIM + oBase + c0;
        #pragma unroll
        for (int c = 0; c < 4; c++) {
            ull o2 = mul2(add2(acc2[r][c], bb2[c]), sc2);
            *(ull*)(dst + 2 * c) = o2;   // STG.64 of two packed floats
        }
    }
}

// ---------------------------------------------------------------------------
// K2: per-token attention scores + entmax bisection + att@V^T (packed f32x2).
// 4 tokens per CTA, 64 threads per token, one score row per thread in regs.
// ---------------------------------------------------------------------------
__global__ __launch_bounds__(256) void k_attn(const float* __restrict__ alpha_p)
{
    __shared__ float kv[4][1024];   // per local token: k[0:512), v[512:1024)
    const int tid   = threadIdx.x;
    const int tok0  = blockIdx.x * 4;
    const int lt    = tid >> 6;
    const int i     = tid & 63;
    const int token = tok0 + lt;

    {   // cooperative load of k,v for 4 tokens
        int f = tid;
        #pragma unroll
        for (int rep = 0; rep < 4; rep++, f += 256) {
            int t    = f >> 8;
            int idx4 = f & 255;
            float4 v = *(const float4*)(g_qkv + (size_t)(tok0 + t) * QKVDIM + 512 + idx4 * 4);
            *(float4*)(&kv[t][idx4 * 4]) = v;
        }
    }
    float q[NH];
    #pragma unroll
    for (int h = 0; h < NH; h++)
        q[h] = g_qkv[(size_t)token * QKVDIM + h * 64 + i];
    __syncthreads();

    const float am1 = alpha_p[0] - 1.f;
    const float inv = 1.f / am1;
    const bool fast = fabsf(inv - 2.f) < 1e-4f;

    // Xa row as 32 packed pairs
    ull xa2[32];
    #pragma unroll
    for (int p = 0; p < 32; p++) xa2[p] = 0ULL;
    #pragma unroll
    for (int h = 0; h < NH; h++) {
        ull q2 = dup2(q[h]);
        const float4* krow = (const float4*)&kv[lt][h * 64];
        #pragma unroll
        for (int j4 = 0; j4 < 16; j4++) {
            float4 kk = krow[j4];
            ffma2(xa2[j4 * 2 + 0], q2, pack2(kk.x, kk.y));
            ffma2(xa2[j4 * 2 + 1], q2, pack2(kk.z, kk.w));
        }
    }

    // row max
    float mx = -3.4e38f;
    #pragma unroll
    for (int p = 0; p < 32; p++)
        mx = fmaxf(mx, fmaxf(lo2(xa2[p]), hi2(xa2[p])));

    float tau_lo = mx - 1.f;
    float dm     = 1.f - exp2f(-6.f * am1);   // 1 - (1/64)^am1
    float tau_m  = tau_lo;

    if (fast) {
        float f_lo;
        {
            ull nt = dup2(-tau_lo);
            ull a0 = pack2(-1.f, 0.f), a1 = 0ULL, a2 = 0ULL, a3 = 0ULL;
            #pragma unroll
            for (int j = 0; j < 8; j++) {
                ull t;
                t = relu2_add(xa2[j],      nt); ffma2(a0, t, t);
                t = relu2_add(xa2[j +  8], nt); ffma2(a1, t, t);
                t = relu2_add(xa2[j + 16], nt); ffma2(a2, t, t);
                t = relu2_add(xa2[j + 24], nt); ffma2(a3, t, t);
            }
            f_lo = hsum2(add2(add2(a0, a1), add2(a2, a3)));
        }
        for (int it = 0; it < NITER; it++) {
            dm *= 0.5f;
            tau_m = tau_lo + dm;
            ull nt = dup2(-tau_m);
            ull a0 = pack2(-1.f, 0.f), a1 = 0ULL, a2 = 0ULL, a3 = 0ULL;
            #pragma unroll
            for (int j = 0; j < 8; j++) {
                ull t;
                t = relu2_add(xa2[j],      nt); ffma2(a0, t, t);
                t = relu2_add(xa2[j +  8], nt); ffma2(a1, t, t);
                t = relu2_add(xa2[j + 16], nt); ffma2(a2, t, t);
                t = relu2_add(xa2[j + 24], nt); ffma2(a3, t, t);
            }
            float fm = hsum2(add2(add2(a0, a1), add2(a2, a3)));
            if (fm * f_lo >= 0.f) tau_lo = tau_m;
        }
        // p and normalize
        {
            ull nt = dup2(-tau_m);
            ull s0 = 0ULL, s1 = 0ULL;
            #pragma unroll
            for (int p = 0; p < 16; p++) {
                ull t0 = relu2_add(xa2[p],      nt);
                ull t1 = relu2_add(xa2[p + 16], nt);
                ull p0 = mul2(t0, t0);
                ull p1 = mul2(t1, t1);
                xa2[p]      = p0;
                xa2[p + 16] = p1;
                ffma2(s0, t0, t0);
                ffma2(s1, t1, t1);
            }
            float rs = 1.f / hsum2(add2(s0, s1));
            ull rs2 = dup2(rs);
            #pragma unroll
            for (int p = 0; p < 32; p++) xa2[p] = mul2(xa2[p], rs2);
        }
    } else {
        // general-alpha fallback: p(z) = clamp(z,0)^(1/(alpha-1)) (scalar)
        float xs[64];
        #pragma unroll
        for (int p = 0; p < 32; p++) { xs[2 * p] = lo2(xa2[p]); xs[2 * p + 1] = hi2(xa2[p]); }
        float f_lo = -1.f;
        #pragma unroll
        for (int j = 0; j < 64; j++) {
            float z = xs[j] - tau_lo;
            f_lo += (z > 0.f) ? powf(fmaxf(z, 1e-30f), inv) : 0.f;
        }
        for (int it = 0; it < NITER; it++) {
            dm *= 0.5f;
            tau_m = tau_lo + dm;
            float fm = -1.f;
            #pragma unroll
            for (int j = 0; j < 64; j++) {
                float z = xs[j] - tau_m;
                fm += (z > 0.f) ? powf(fmaxf(z, 1e-30f), inv) : 0.f;
            }
            if (fm * f_lo >= 0.f) tau_lo = tau_m;
        }
        float s = 0.f;
        #pragma unroll
        for (int j = 0; j < 64; j++) {
            float z = xs[j] - tau_m;
            float p = (z > 0.f) ? powf(fmaxf(z, 1e-30f), inv) : 0.f;
            xs[j] = p;
            s += p;
        }
        float rs = 1.f / s;
        #pragma unroll
        for (int p = 0; p < 32; p++) xa2[p] = pack2(xs[2 * p] * rs, xs[2 * p + 1] * rs);
    }

    // res[h][i] = sum_j att[i][j] * v[h][j]
    #pragma unroll
    for (int h = 0; h < NH; h++) {
        const float4* vrow = (const float4*)&kv[lt][512 + h * 64];
        ull c0 = 0ULL, c1 = 0ULL;
        #pragma unroll
        for (int j4 = 0; j4 < 8; j4++) {
            float4 v0 = vrow[j4];
            float4 v1 = vrow[j4 + 8];
            ffma2(c0, xa2[j4 * 2 + 0],      pack2(v0.x, v0.y));
            ffma2(c0, xa2[j4 * 2 + 1],      pack2(v0.z, v0.w));
            ffma2(c1, xa2[16 + j4 * 2 + 0], pack2(v1.x, v1.y));
            ffma2(c1, xa2[16 + j4 * 2 + 1], pack2(v1.z, v1.w));
        }
        g_res[(size_t)token * HE + h * 64 + i] = hsum2(add2(c0, c1));
    }
}

// ---------------------------------------------------------------------------
// K3: output projection.  out[n,o] = sum_k res[n,k]*Wu[o,k] + bu[o]
// Tile: M=128, N=64, K=512 in 16 chunks of 32. 4 row-pairs x 4 cols (FFMA2).
// ---------------------------------------------------------------------------
__global__ __launch_bounds__(256) void k_out(
    const float* __restrict__ Wu, const float* __restrict__ bu,
    float* __restrict__ out)
{
    __shared__ float aT[32][132];  // aT[k][m]
    __shared__ float bT[32][68];   // bT[k][o]
    const int tid = threadIdx.x;
    const int bm  = blockIdx.x;    // 0..127
    const int m0  = (tid >> 4) * 8;
    const int c0  = (tid & 15) * 4;

    ull acc2[4][4];                // [row-pair][col]
    #pragma unroll
    for (int r = 0; r < 4; r++)
        #pragma unroll
        for (int c = 0; c < 4; c++) acc2[r][c] = 0ULL;

    for (int kc = 0; kc < 16; kc++) {
        __syncthreads();
        {   // A chunk: 128 rows x 32 k
            int f = tid;
            #pragma unroll
            for (int rep = 0; rep < 4; rep++, f += 256) {
                int m  = f >> 3;
                int c4 = f & 7;
                float4 v = *(const float4*)(g_res + (size_t)(bm * 128 + m) * HE + kc * 32 + c4 * 4);
                aT[c4 * 4 + 0][m] = v.x;
                aT[c4 * 4 + 1][m] = v.y;
                aT[c4 * 4 + 2][m] = v.z;
                aT[c4 * 4 + 3][m] = v.w;
            }
        }
        {   // B chunk: 64 o x 32 k
            int f = tid;
            #pragma unroll
            for (int rep = 0; rep < 2; rep++, f += 256) {
                int o  = f >> 3;
                int c4 = f & 7;
                float4 v = *(const float4*)(Wu + (size_t)o * HE + kc * 32 + c4 * 4);
                bT[c4 * 4 + 0][o] = v.x;
                bT[c4 * 4 + 1][o] = v.y;
                bT[c4 * 4 + 2][o] = v.z;
                bT[c4 * 4 + 3][o] = v.w;
            }
        }
        __syncthreads();

        #pragma unroll 8
        for (int k = 0; k < 32; k++) {
            float4 a4a = *(const float4*)&aT[k][m0];
            float4 a4b = *(const float4*)&aT[k][m0 + 4];
            float4 b4  = *(const float4*)&bT[k][c0];
            ull ap[4] = {pack2(a4a.x, a4a.y), pack2(a4a.z, a4a.w),
                         pack2(a4b.x, a4b.y), pack2(a4b.z, a4b.w)};
            float b[4] = {b4.x, b4.y, b4.z, b4.w};
            #pragma unroll
            for (int c = 0; c < 4; c++) {
                ull bd = dup2(b[c]);
                #pragma unroll
                for (int r = 0; r < 4; r++) ffma2(acc2[r][c], ap[r], bd);
            }
        }
    }

    float4 bb = *(const float4*)(bu + c0);
    float bbv[4] = {bb.x, bb.y, bb.z, bb.w};
    #pragma unroll
    for (int rp = 0; rp < 4; rp++) {
        float4 oe, oo;
        float* pe = &oe.x; float* po = &oo.x;
        #pragma unroll
        for (int c = 0; c < 4; c++) {
            pe[c] = lo2(acc2[rp][c]) + bbv[c];
            po[c] = hi2(acc2[rp][c]) + bbv[c];
        }
        *(float4*)(out + (size_t)(bm * 128 + m0 + 2 * rp)     * 64 + c0) = oe;
        *(float4*)(out + (size_t)(bm * 128 + m0 + 2 * rp + 1) * 64 + c0) = oo;
    }
}

// ---------------------------------------------------------------------------
extern "C" void kernel_launch(void* const* d_in, const int* in_sizes, int n_in,
                              void* d_out, int out_size)
{
    const float* x     = (const float*)d_in[0];
    const float* alpha = (const float*)d_in[1];
    const float* Wk    = (const float*)d_in[2];
    const float* bk    = (const float*)d_in[3];
    const float* Wq    = (const float*)d_in[4];
    const float* bq    = (const float*)d_in[5];
    const float* Wv    = (const float*)d_in[6];
    const float* bv    = (const float*)d_in[7];
    const float* Wu    = (const float*)d_in[8];
    const float* bu    = (const float*)d_in[9];
    float* out = (float*)d_out;

    k_qkv<<<dim3(128, 12), 256>>>(x, Wq, bq, Wk, bk, Wv, bv, alpha);
    k_attn<<<NTOK / 4, 256>>>(alpha);
    k_out<<<NTOK / 128, 256>>>(Wu, bu, out);
}

// round 7
// speedup vs baseline: 1.1355x; 1.1355x over previous
#include <cuda_runtime.h>
#include <math.h>

#define NTOK   16384
#define NH     8
#define HE     512
#define QKVDIM 1536
#define NEWTON 7
#define NITER  16   // general-alpha fallback bisection count

typedef unsigned long long ull;

// Scratch (static device memory — allocation-free)
__device__ float g_qkv[NTOK * QKVDIM];   // q (pre-scaled) | k | v
__device__ float g_res[NTOK * HE];

// ---------------- f32x2 packed-math helpers --------------------------------
__device__ __forceinline__ ull pack2(float lo, float hi) {
    ull r; asm("mov.b64 %0, {%1, %2};" : "=l"(r) : "f"(lo), "f"(hi)); return r;
}
__device__ __forceinline__ ull dup2(float v) { return pack2(v, v); }
__device__ __forceinline__ float lo2(ull v) {
    float f; asm("{ .reg .b32 hi; mov.b64 {%0, hi}, %1; }" : "=f"(f) : "l"(v)); return f;
}
__device__ __forceinline__ float hi2(ull v) {
    float f; asm("{ .reg .b32 lo; mov.b64 {lo, %0}, %1; }" : "=f"(f) : "l"(v)); return f;
}
__device__ __forceinline__ void ffma2(ull& d, ull a, ull b) {
    asm("fma.rn.f32x2 %0, %1, %2, %0;" : "+l"(d) : "l"(a), "l"(b));
}
__device__ __forceinline__ ull add2(ull a, ull b) {
    ull r; asm("add.rn.f32x2 %0, %1, %2;" : "=l"(r) : "l"(a), "l"(b)); return r;
}
__device__ __forceinline__ ull mul2(ull a, ull b) {
    ull r; asm("mul.rn.f32x2 %0, %1, %2;" : "=l"(r) : "l"(a), "l"(b)); return r;
}
__device__ __forceinline__ float hsum2(ull v) { return lo2(v) + hi2(v); }
__device__ __forceinline__ ull relu2_add(ull x2, ull nt2) {
    ull r;
    asm("{\n\t"
        ".reg .f32 lo, hi;\n\t"
        "add.rn.f32x2 %0, %1, %2;\n\t"
        "mov.b64 {lo, hi}, %0;\n\t"
        "max.f32 lo, lo, 0f00000000;\n\t"
        "max.f32 hi, hi, 0f00000000;\n\t"
        "mov.b64 %0, {lo, hi};\n\t"
        "}" : "=l"(r) : "l"(x2), "l"(nt2));
    return r;
}

// ---------------------------------------------------------------------------
// K1: fused QKV projection (scalar FFMA — measured best at 97 µs).
// Tile: M=128 x N=128, K=64 in 2 chunks of 32, 8x8 per thread, padded smem.
// ---------------------------------------------------------------------------
__global__ __launch_bounds__(256, 2) void k_qkv(
    const float* __restrict__ x,
    const float* __restrict__ Wq, const float* __restrict__ bq,
    const float* __restrict__ Wk, const float* __restrict__ bk,
    const float* __restrict__ Wv, const float* __restrict__ bv,
    const float* __restrict__ alpha_p)
{
    __shared__ float aT[32][132];   // aT[k][m]
    __shared__ float bT[32][132];   // bT[k][o]
    const int tid   = threadIdx.x;
    const int bm    = blockIdx.x;
    const int oBase = blockIdx.y * 128;

    const float* W; const float* bias;
    if (oBase < 512)       { W = Wq; bias = bq; }
    else if (oBase < 1024) { W = Wk; bias = bk; }
    else                   { W = Wv; bias = bv; }
    const int wBase = oBase & 511;

    const int r0 = (tid >> 4) * 8;
    const int c0 = (tid & 15) * 8;

    float acc[8][8];
    #pragma unroll
    for (int r = 0; r < 8; r++)
        #pragma unroll
        for (int c = 0; c < 8; c++) acc[r][c] = 0.f;

    #pragma unroll
    for (int kc = 0; kc < 2; kc++) {
        __syncthreads();
        {
            int f = tid;
            #pragma unroll
            for (int rep = 0; rep < 4; rep++, f += 256) {
                int row = f >> 3;
                int c4  = f & 7;
                float4 v = *(const float4*)(x + (size_t)(bm * 128 + row) * 64 + kc * 32 + c4 * 4);
                aT[c4 * 4 + 0][row] = v.x;
                aT[c4 * 4 + 1][row] = v.y;
                aT[c4 * 4 + 2][row] = v.z;
                aT[c4 * 4 + 3][row] = v.w;
            }
        }
        {
            int f = tid;
            #pragma unroll
            for (int rep = 0; rep < 4; rep++, f += 256) {
                int o  = f >> 3;
                int c4 = f & 7;
                float4 v = *(const float4*)(W + (size_t)(wBase + o) * 64 + kc * 32 + c4 * 4);
                bT[c4 * 4 + 0][o] = v.x;
                bT[c4 * 4 + 1][o] = v.y;
                bT[c4 * 4 + 2][o] = v.z;
                bT[c4 * 4 + 3][o] = v.w;
            }
        }
        __syncthreads();

        #pragma unroll 8
        for (int k = 0; k < 32; k++) {
            float4 a0 = *(const float4*)&aT[k][r0];
            float4 a1 = *(const float4*)&aT[k][r0 + 4];
            float4 b0 = *(const float4*)&bT[k][c0];
            float4 b1 = *(const float4*)&bT[k][c0 + 4];
            float a[8] = {a0.x, a0.y, a0.z, a0.w, a1.x, a1.y, a1.z, a1.w};
            float b[8] = {b0.x, b0.y, b0.z, b0.w, b1.x, b1.y, b1.z, b1.w};
            #pragma unroll
            for (int r = 0; r < 8; r++)
                #pragma unroll
                for (int c = 0; c < 8; c++)
                    acc[r][c] = fmaf(a[r], b[c], acc[r][c]);
        }
    }

    const float am1   = alpha_p[0] - 1.f;
    const float scale = (oBase < 512) ? am1 * 0.125f : 1.f;

    float bb[8];
    #pragma unroll
    for (int c = 0; c < 8; c++) bb[c] = bias[wBase + c0 + c];

    #pragma unroll
    for (int r = 0; r < 8; r++) {
        float o[8];
        #pragma unroll
        for (int c = 0; c < 8; c++) o[c] = (acc[r][c] + bb[c]) * scale;
        float* dst = g_qkv + (size_t)(bm * 128 + r0 + r) * QKVDIM + oBase + c0;
        *(float4*)(dst)     = make_float4(o[0], o[1], o[2], o[3]);
        *(float4*)(dst + 4) = make_float4(o[4], o[5], o[6], o[7]);
    }
}

// ---------------------------------------------------------------------------
// K2: per-token scores + entmax via Newton (alpha=1.5 fast path) + att@V^T.
// f(tau) = sum relu(xa - tau)^2 - 1 is convex decreasing; Newton from
// tau0 = max - 1 (f >= 0) converges monotonically from below. 7 iters
// reach <1e-7 even in the worst (flat) case.
// ---------------------------------------------------------------------------
__global__ __launch_bounds__(256) void k_attn(const float* __restrict__ alpha_p)
{
    __shared__ float kv[4][1024];
    const int tid   = threadIdx.x;
    const int tok0  = blockIdx.x * 4;
    const int lt    = tid >> 6;
    const int i     = tid & 63;
    const int token = tok0 + lt;

    {
        int f = tid;
        #pragma unroll
        for (int rep = 0; rep < 4; rep++, f += 256) {
            int t    = f >> 8;
            int idx4 = f & 255;
            float4 v = *(const float4*)(g_qkv + (size_t)(tok0 + t) * QKVDIM + 512 + idx4 * 4);
            *(float4*)(&kv[t][idx4 * 4]) = v;
        }
    }
    float q[NH];
    #pragma unroll
    for (int h = 0; h < NH; h++)
        q[h] = g_qkv[(size_t)token * QKVDIM + h * 64 + i];
    __syncthreads();

    const float am1 = alpha_p[0] - 1.f;
    const float inv = 1.f / am1;
    const bool fast = fabsf(inv - 2.f) < 1e-4f;

    // Xa row as 32 packed pairs
    ull xa2[32];
    #pragma unroll
    for (int p = 0; p < 32; p++) xa2[p] = 0ULL;
    #pragma unroll
    for (int h = 0; h < NH; h++) {
        ull q2 = dup2(q[h]);
        const float4* krow = (const float4*)&kv[lt][h * 64];
        #pragma unroll
        for (int j4 = 0; j4 < 16; j4++) {
            float4 kk = krow[j4];
            ffma2(xa2[j4 * 2 + 0], q2, pack2(kk.x, kk.y));
            ffma2(xa2[j4 * 2 + 1], q2, pack2(kk.z, kk.w));
        }
    }

    float mx = -3.4e38f;
    #pragma unroll
    for (int p = 0; p < 32; p++)
        mx = fmaxf(mx, fmaxf(lo2(xa2[p]), hi2(xa2[p])));

    float tau = mx - 1.f;

    if (fast) {
        // -------- Newton iterations --------
        for (int it = 0; it < NEWTON; it++) {
            ull nt = dup2(-tau);
            ull s2a = 0ULL, s2b = 0ULL, s2c = 0ULL, s2d = 0ULL;   // sum t^2
            ull s1a = 0ULL, s1b = 0ULL, s1c = 0ULL, s1d = 0ULL;   // sum t
            #pragma unroll
            for (int j = 0; j < 8; j++) {
                ull t;
                t = relu2_add(xa2[j],      nt); ffma2(s2a, t, t); s1a = add2(s1a, t);
                t = relu2_add(xa2[j +  8], nt); ffma2(s2b, t, t); s1b = add2(s1b, t);
                t = relu2_add(xa2[j + 16], nt); ffma2(s2c, t, t); s1c = add2(s1c, t);
                t = relu2_add(xa2[j + 24], nt); ffma2(s2d, t, t); s1d = add2(s1d, t);
            }
            float f  = hsum2(add2(add2(s2a, s2b), add2(s2c, s2d))) - 1.f;
            float s1 = hsum2(add2(add2(s1a, s1b), add2(s1c, s1d)));
            s1 = fmaxf(s1, 1e-20f);
            tau += __fdividef(f, 2.f * s1);    // step = -f/f', f' = -2*s1
        }
        // -------- p = relu(xa - tau)^2, normalize --------
        {
            ull nt = dup2(-tau);
            ull s0 = 0ULL, s1 = 0ULL;
            #pragma unroll
            for (int p = 0; p < 16; p++) {
                ull t0 = relu2_add(xa2[p],      nt);
                ull t1 = relu2_add(xa2[p + 16], nt);
                xa2[p]      = mul2(t0, t0);
                xa2[p + 16] = mul2(t1, t1);
                ffma2(s0, t0, t0);
                ffma2(s1, t1, t1);
            }
            float rs = 1.f / hsum2(add2(s0, s1));
            ull rs2 = dup2(rs);
            #pragma unroll
            for (int p = 0; p < 32; p++) xa2[p] = mul2(xa2[p], rs2);
        }
    } else {
        // general-alpha fallback: bisection with powf
        float xs[64];
        #pragma unroll
        for (int p = 0; p < 32; p++) { xs[2 * p] = lo2(xa2[p]); xs[2 * p + 1] = hi2(xa2[p]); }
        float tau_lo = mx - 1.f;
        float dm     = 1.f - exp2f(-6.f * am1);
        float tau_m  = tau_lo;
        float f_lo = -1.f;
        #pragma unroll
        for (int j = 0; j < 64; j++) {
            float z = xs[j] - tau_lo;
            f_lo += (z > 0.f) ? powf(fmaxf(z, 1e-30f), inv) : 0.f;
        }
        for (int it = 0; it < NITER; it++) {
            dm *= 0.5f;
            tau_m = tau_lo + dm;
            float fm = -1.f;
            #pragma unroll
            for (int j = 0; j < 64; j++) {
                float z = xs[j] - tau_m;
                fm += (z > 0.f) ? powf(fmaxf(z, 1e-30f), inv) : 0.f;
            }
            if (fm * f_lo >= 0.f) tau_lo = tau_m;
        }
        float s = 0.f;
        #pragma unroll
        for (int j = 0; j < 64; j++) {
            float z = xs[j] - tau_m;
            float p = (z > 0.f) ? powf(fmaxf(z, 1e-30f), inv) : 0.f;
            xs[j] = p;
            s += p;
        }
        float rs = 1.f / s;
        #pragma unroll
        for (int p = 0; p < 32; p++) xa2[p] = pack2(xs[2 * p] * rs, xs[2 * p + 1] * rs);
    }

    // res[h][i] = sum_j att[i][j] * v[h][j]
    #pragma unroll
    for (int h = 0; h < NH; h++) {
        const float4* vrow = (const float4*)&kv[lt][512 + h * 64];
        ull c0 = 0ULL, c1 = 0ULL;
        #pragma unroll
        for (int j4 = 0; j4 < 8; j4++) {
            float4 v0 = vrow[j4];
            float4 v1 = vrow[j4 + 8];
            ffma2(c0, xa2[j4 * 2 + 0],      pack2(v0.x, v0.y));
            ffma2(c0, xa2[j4 * 2 + 1],      pack2(v0.z, v0.w));
            ffma2(c1, xa2[16 + j4 * 2 + 0], pack2(v1.x, v1.y));
            ffma2(c1, xa2[16 + j4 * 2 + 1], pack2(v1.z, v1.w));
        }
        g_res[(size_t)token * HE + h * 64 + i] = hsum2(add2(c0, c1));
    }
}

// ---------------------------------------------------------------------------
// K3: output projection (packed f32x2).  Tile M=128 x N=64, K=512 in 16x32.
// ---------------------------------------------------------------------------
__global__ __launch_bounds__(256) void k_out(
    const float* __restrict__ Wu, const float* __restrict__ bu,
    float* __restrict__ out)
{
    __shared__ float aT[32][132];
    __shared__ float bT[32][68];
    const int tid = threadIdx.x;
    const int bm  = blockIdx.x;
    const int m0  = (tid >> 4) * 8;
    const int c0  = (tid & 15) * 4;

    ull acc2[4][4];
    #pragma unroll
    for (int r = 0; r < 4; r++)
        #pragma unroll
        for (int c = 0; c < 4; c++) acc2[r][c] = 0ULL;

    for (int kc = 0; kc < 16; kc++) {
        __syncthreads();
        {
            int f = tid;
            #pragma unroll
            for (int rep = 0; rep < 4; rep++, f += 256) {
                int m  = f >> 3;
                int c4 = f & 7;
                float4 v = *(const float4*)(g_res + (size_t)(bm * 128 + m) * HE + kc * 32 + c4 * 4);
                aT[c4 * 4 + 0][m] = v.x;
                aT[c4 * 4 + 1][m] = v.y;
                aT[c4 * 4 + 2][m] = v.z;
                aT[c4 * 4 + 3][m] = v.w;
            }
        }
        {
            int f = tid;
            #pragma unroll
            for (int rep = 0; rep < 2; rep++, f += 256) {
                int o  = f >> 3;
                int c4 = f & 7;
                float4 v = *(const float4*)(Wu + (size_t)o * HE + kc * 32 + c4 * 4);
                bT[c4 * 4 + 0][o] = v.x;
                bT[c4 * 4 + 1][o] = v.y;
                bT[c4 * 4 + 2][o] = v.z;
                bT[c4 * 4 + 3][o] = v.w;
            }
        }
        __syncthreads();

        #pragma unroll 8
        for (int k = 0; k < 32; k++) {
            float4 a4a = *(const float4*)&aT[k][m0];
            float4 a4b = *(const float4*)&aT[k][m0 + 4];
            float4 b4  = *(const float4*)&bT[k][c0];
            ull ap[4] = {pack2(a4a.x, a4a.y), pack2(a4a.z, a4a.w),
                         pack2(a4b.x, a4b.y), pack2(a4b.z, a4b.w)};
            float b[4] = {b4.x, b4.y, b4.z, b4.w};
            #pragma unroll
            for (int c = 0; c < 4; c++) {
                ull bd = dup2(b[c]);
                #pragma unroll
                for (int r = 0; r < 4; r++) ffma2(acc2[r][c], ap[r], bd);
            }
        }
    }

    float4 bb = *(const float4*)(bu + c0);
    float bbv[4] = {bb.x, bb.y, bb.z, bb.w};
    #pragma unroll
    for (int rp = 0; rp < 4; rp++) {
        float4 oe, oo;
        float* pe = &oe.x; float* po = &oo.x;
        #pragma unroll
        for (int c = 0; c < 4; c++) {
            pe[c] = lo2(acc2[rp][c]) + bbv[c];
            po[c] = hi2(acc2[rp][c]) + bbv[c];
        }
        *(float4*)(out + (size_t)(bm * 128 + m0 + 2 * rp)     * 64 + c0) = oe;
        *(float4*)(out + (size_t)(bm * 128 + m0 + 2 * rp + 1) * 64 + c0) = oo;
    }
}

// ---------------------------------------------------------------------------
extern "C" void kernel_launch(void* const* d_in, const int* in_sizes, int n_in,
                              void* d_out, int out_size)
{
    const float* x     = (const float*)d_in[0];
    const float* alpha = (const float*)d_in[1];
    const float* Wk    = (const float*)d_in[2];
    const float* bk    = (const float*)d_in[3];
    const float* Wq    = (const float*)d_in[4];
    const float* bq    = (const float*)d_in[5];
    const float* Wv    = (const float*)d_in[6];
    const float* bv    = (const float*)d_in[7];
    const float* Wu    = (const float*)d_in[8];
    const float* bu    = (const float*)d_in[9];
    float* out = (float*)d_out;

    k_qkv<<<dim3(128, 12), 256>>>(x, Wq, bq, Wk, bk, Wv, bv, alpha);
    k_attn<<<NTOK / 4, 256>>>(alpha);
    k_out<<<NTOK / 128, 256>>>(Wu, bu, out);
}

// round 9
// speedup vs baseline: 1.4188x; 1.2494x over previous
#include <cuda_runtime.h>
#include <cuda_bf16.h>
#include <math.h>
#include <stdint.h>

#define NTOK   16384
#define NH     8
#define HE     512
#define QKVDIM 1536
#define NEWTON 7
#define NITER  16

typedef unsigned long long ull;

// Scratch (static device memory — allocation-free)
__device__ float         g_qkv[NTOK * QKVDIM];  // q (pre-scaled) | k | v
__device__ __nv_bfloat16 g_res_hi[NTOK * HE];
__device__ __nv_bfloat16 g_res_lo[NTOK * HE];

// ======================= helpers ===========================================
__device__ __forceinline__ uint32_t smem_u32(const void* p) {
    uint32_t a;
    asm("{ .reg .u64 t; cvta.to.shared.u64 t, %1; cvt.u32.u64 %0, t; }" : "=r"(a) : "l"(p));
    return a;
}
__device__ __forceinline__ void ldsm4(uint32_t& r0, uint32_t& r1, uint32_t& r2, uint32_t& r3,
                                      uint32_t a) {
    asm volatile("ldmatrix.sync.aligned.m8n8.x4.shared.b16 {%0,%1,%2,%3}, [%4];"
                 : "=r"(r0), "=r"(r1), "=r"(r2), "=r"(r3) : "r"(a));
}
__device__ __forceinline__ void mma16816(float* d, uint32_t a0, uint32_t a1, uint32_t a2,
                                         uint32_t a3, uint32_t b0, uint32_t b1) {
    asm volatile(
        "mma.sync.aligned.m16n8k16.row.col.f32.bf16.bf16.f32 "
        "{%0,%1,%2,%3}, {%4,%5,%6,%7}, {%8,%9}, {%0,%1,%2,%3};"
        : "+f"(d[0]), "+f"(d[1]), "+f"(d[2]), "+f"(d[3])
        : "r"(a0), "r"(a1), "r"(a2), "r"(a3), "r"(b0), "r"(b1));
}
// bf16 hi/lo split of two fp32, packed bf16x2 words
__device__ __forceinline__ void split2(float a, float b, uint32_t& hp, uint32_t& lp) {
    __nv_bfloat162 h = __floats2bfloat162_rn(a, b);
    float2 hf = __bfloat1622float2(h);
    __nv_bfloat162 l = __floats2bfloat162_rn(a - hf.x, b - hf.y);
    hp = *reinterpret_cast<uint32_t*>(&h);
    lp = *reinterpret_cast<uint32_t*>(&l);
}

// ---------------- f32x2 packed-math helpers (k_attn) -----------------------
__device__ __forceinline__ ull pack2(float lo, float hi) {
    ull r; asm("mov.b64 %0, {%1, %2};" : "=l"(r) : "f"(lo), "f"(hi)); return r;
}
__device__ __forceinline__ ull dup2(float v) { return pack2(v, v); }
__device__ __forceinline__ float lo2(ull v) {
    float f; asm("{ .reg .b32 hi; mov.b64 {%0, hi}, %1; }" : "=f"(f) : "l"(v)); return f;
}
__device__ __forceinline__ float hi2(ull v) {
    float f; asm("{ .reg .b32 lo; mov.b64 {lo, %0}, %1; }" : "=f"(f) : "l"(v)); return f;
}
__device__ __forceinline__ void ffma2(ull& d, ull a, ull b) {
    asm("fma.rn.f32x2 %0, %1, %2, %0;" : "+l"(d) : "l"(a), "l"(b));
}
__device__ __forceinline__ ull add2(ull a, ull b) {
    ull r; asm("add.rn.f32x2 %0, %1, %2;" : "=l"(r) : "l"(a), "l"(b)); return r;
}
__device__ __forceinline__ ull mul2(ull a, ull b) {
    ull r; asm("mul.rn.f32x2 %0, %1, %2;" : "=l"(r) : "l"(a), "l"(b)); return r;
}
__device__ __forceinline__ float hsum2(ull v) { return lo2(v) + hi2(v); }
__device__ __forceinline__ ull relu2_add(ull x2, ull nt2) {
    ull r;
    asm("{\n\t"
        ".reg .f32 lo, hi;\n\t"
        "add.rn.f32x2 %0, %1, %2;\n\t"
        "mov.b64 {lo, hi}, %0;\n\t"
        "max.f32 lo, lo, 0f00000000;\n\t"
        "max.f32 hi, hi, 0f00000000;\n\t"
        "mov.b64 %0, {lo, hi};\n\t"
        "}" : "=l"(r) : "l"(x2), "l"(nt2));
    return r;
}

// ---------------------------------------------------------------------------
// K1 (mma.sync bf16 split): QKV projection.
// CTA = 128 tokens x 64 outputs. A,B hi/lo resident in smem (48 KB).
// 3 passes: Ah*Bh + Al*Bh + Ah*Bl. Warp grid 4(M) x 2(N); 2 mt x 4 nt each.
// ---------------------------------------------------------------------------
__global__ __launch_bounds__(256) void k_qkv(
    const float* __restrict__ x,
    const float* __restrict__ Wq, const float* __restrict__ bq,
    const float* __restrict__ Wk, const float* __restrict__ bk,
    const float* __restrict__ Wv, const float* __restrict__ bv,
    const float* __restrict__ alpha_p)
{
    __shared__ __align__(16) __nv_bfloat16 sA[2][128 * 64];  // 32 KB
    __shared__ __align__(16) __nv_bfloat16 sB[2][64 * 64];   // 16 KB
    const int tid  = threadIdx.x;
    const int bm   = blockIdx.x;
    const int tn   = blockIdx.y;            // 0..23
    const int oBase = tn * 64;

    const float* W; const float* bias;
    if (tn < 8)       { W = Wq; bias = bq; }
    else if (tn < 16) { W = Wk; bias = bk; }
    else              { W = Wv; bias = bv; }
    const int wBase = oBase & 511;

    // ---- load A (x tile): 128 rows x 8 chunks of 16B, hi+lo, swizzled ----
    for (int idx = tid; idx < 1024; idx += 256) {
        int row = idx >> 3, c = idx & 7;
        const float* src = x + (size_t)(bm * 128 + row) * 64 + c * 8;
        float4 v0 = *(const float4*)src;
        float4 v1 = *(const float4*)(src + 4);
        uint4 hh, ll;
        split2(v0.x, v0.y, hh.x, ll.x);
        split2(v0.z, v0.w, hh.y, ll.y);
        split2(v1.x, v1.y, hh.z, ll.z);
        split2(v1.z, v1.w, hh.w, ll.w);
        int off = row * 8 + (c ^ (row & 7));
        ((uint4*)sA[0])[off] = hh;
        ((uint4*)sA[1])[off] = ll;
    }
    // ---- load B (W tile): 64 rows x 8 chunks, hi+lo ----
    for (int idx = tid; idx < 512; idx += 256) {
        int row = idx >> 3, c = idx & 7;
        const float* src = W + (size_t)(wBase + row) * 64 + c * 8;
        float4 v0 = *(const float4*)src;
        float4 v1 = *(const float4*)(src + 4);
        uint4 hh, ll;
        split2(v0.x, v0.y, hh.x, ll.x);
        split2(v0.z, v0.w, hh.y, ll.y);
        split2(v1.x, v1.y, hh.z, ll.z);
        split2(v1.z, v1.w, hh.w, ll.w);
        int off = row * 8 + (c ^ (row & 7));
        ((uint4*)sB[0])[off] = hh;
        ((uint4*)sB[1])[off] = ll;
    }
    __syncthreads();

    const int wid   = tid >> 5, lane = tid & 31;
    const int warpM = wid >> 1, warpN = wid & 1;

    float acc[2][4][4];
    #pragma unroll
    for (int m = 0; m < 2; m++)
        #pragma unroll
        for (int n = 0; n < 4; n++)
            #pragma unroll
            for (int k = 0; k < 4; k++) acc[m][n][k] = 0.f;

    const uint32_t aB[2] = { smem_u32(sA[0]), smem_u32(sA[1]) };
    const uint32_t bB[2] = { smem_u32(sB[0]), smem_u32(sB[1]) };
    const int pa[3] = {0, 1, 0}, pb[3] = {0, 0, 1};

    const int arow0 = warpM * 32 + (lane & 15);
    const int brow0 = warpN * 32 + (lane & 15);
    const int chi   = lane >> 4;

    #pragma unroll
    for (int p = 0; p < 3; p++) {
        uint32_t ab = aB[pa[p]], bb = bB[pb[p]];
        #pragma unroll
        for (int kk = 0; kk < 4; kk++) {
            int cc = kk * 2 + chi;
            uint32_t a0, a1, a2, a3, a4, a5, a6, a7;
            { int r = arow0;      ldsm4(a0, a1, a2, a3, ab + ((r * 8 + (cc ^ (r & 7))) << 4)); }
            { int r = arow0 + 16; ldsm4(a4, a5, a6, a7, ab + ((r * 8 + (cc ^ (r & 7))) << 4)); }
            uint32_t b0, b1, b2, b3, b4, b5, b6, b7;
            { int r = brow0;      ldsm4(b0, b1, b2, b3, bb + ((r * 8 + (cc ^ (r & 7))) << 4)); }
            { int r = brow0 + 16; ldsm4(b4, b5, b6, b7, bb + ((r * 8 + (cc ^ (r & 7))) << 4)); }
            mma16816(acc[0][0], a0, a1, a2, a3, b0, b2);
            mma16816(acc[0][1], a0, a1, a2, a3, b1, b3);
            mma16816(acc[0][2], a0, a1, a2, a3, b4, b6);
            mma16816(acc[0][3], a0, a1, a2, a3, b5, b7);
            mma16816(acc[1][0], a4, a5, a6, a7, b0, b2);
            mma16816(acc[1][1], a4, a5, a6, a7, b1, b3);
            mma16816(acc[1][2], a4, a5, a6, a7, b4, b6);
            mma16816(acc[1][3], a4, a5, a6, a7, b5, b7);
        }
    }

    // ---- epilogue: bias + scale, float2 stores ----
    const float am1   = __ldg(alpha_p) - 1.f;
    const float scale = (tn < 8) ? am1 * 0.125f : 1.f;
    const int rbase = bm * 128 + warpM * 32 + (lane >> 2);
    const int cbase = warpN * 32 + (lane & 3) * 2;
    #pragma unroll
    for (int mt = 0; mt < 2; mt++)
        #pragma unroll
        for (int nt = 0; nt < 4; nt++) {
            int col = cbase + nt * 8;
            float bv0 = __ldg(&bias[wBase + col]);
            float bv1 = __ldg(&bias[wBase + col + 1]);
            int row0 = rbase + mt * 16;
            float2 e0 = make_float2((acc[mt][nt][0] + bv0) * scale,
                                    (acc[mt][nt][1] + bv1) * scale);
            float2 e1 = make_float2((acc[mt][nt][2] + bv0) * scale,
                                    (acc[mt][nt][3] + bv1) * scale);
            *(float2*)(g_qkv + (size_t)row0 * QKVDIM + oBase + col)       = e0;
            *(float2*)(g_qkv + (size_t)(row0 + 8) * QKVDIM + oBase + col) = e1;
        }
}

// ---------------------------------------------------------------------------
// K2: per-token scores + entmax via Newton + att@V^T. Emits bf16 hi/lo res.
// ---------------------------------------------------------------------------
__global__ __launch_bounds__(256) void k_attn(const float* __restrict__ alpha_p)
{
    __shared__ float kv[4][1024];
    const int tid   = threadIdx.x;
    const int tok0  = blockIdx.x * 4;
    const int lt    = tid >> 6;
    const int i     = tid & 63;
    const int token = tok0 + lt;

    {
        int f = tid;
        #pragma unroll
        for (int rep = 0; rep < 4; rep++, f += 256) {
            int t    = f >> 8;
            int idx4 = f & 255;
            float4 v = *(const float4*)(g_qkv + (size_t)(tok0 + t) * QKVDIM + 512 + idx4 * 4);
            *(float4*)(&kv[t][idx4 * 4]) = v;
        }
    }
    float q[NH];
    #pragma unroll
    for (int h = 0; h < NH; h++)
        q[h] = g_qkv[(size_t)token * QKVDIM + h * 64 + i];
    __syncthreads();

    const float am1 = alpha_p[0] - 1.f;
    const float inv = 1.f / am1;
    const bool fast = fabsf(inv - 2.f) < 1e-4f;

    ull xa2[32];
    #pragma unroll
    for (int p = 0; p < 32; p++) xa2[p] = 0ULL;
    #pragma unroll
    for (int h = 0; h < NH; h++) {
        ull q2 = dup2(q[h]);
        const float4* krow = (const float4*)&kv[lt][h * 64];
        #pragma unroll
        for (int j4 = 0; j4 < 16; j4++) {
            float4 kk = krow[j4];
            ffma2(xa2[j4 * 2 + 0], q2, pack2(kk.x, kk.y));
            ffma2(xa2[j4 * 2 + 1], q2, pack2(kk.z, kk.w));
        }
    }

    float mx = -3.4e38f;
    #pragma unroll
    for (int p = 0; p < 32; p++)
        mx = fmaxf(mx, fmaxf(lo2(xa2[p]), hi2(xa2[p])));

    float tau = mx - 1.f;

    if (fast) {
        for (int it = 0; it < NEWTON; it++) {
            ull nt = dup2(-tau);
            ull s2a = 0ULL, s2b = 0ULL, s2c = 0ULL, s2d = 0ULL;
            ull s1a = 0ULL, s1b = 0ULL, s1c = 0ULL, s1d = 0ULL;
            #pragma unroll
            for (int j = 0; j < 8; j++) {
                ull t;
                t = relu2_add(xa2[j],      nt); ffma2(s2a, t, t); s1a = add2(s1a, t);
                t = relu2_add(xa2[j +  8], nt); ffma2(s2b, t, t); s1b = add2(s1b, t);
                t = relu2_add(xa2[j + 16], nt); ffma2(s2c, t, t); s1c = add2(s1c, t);
                t = relu2_add(xa2[j + 24], nt); ffma2(s2d, t, t); s1d = add2(s1d, t);
            }
            float f  = hsum2(add2(add2(s2a, s2b), add2(s2c, s2d))) - 1.f;
            float s1 = hsum2(add2(add2(s1a, s1b), add2(s1c, s1d)));
            s1 = fmaxf(s1, 1e-20f);
            tau += __fdividef(f, 2.f * s1);
        }
        {
            ull nt = dup2(-tau);
            ull s0 = 0ULL, s1 = 0ULL;
            #pragma unroll
            for (int p = 0; p < 16; p++) {
                ull t0 = relu2_add(xa2[p],      nt);
                ull t1 = relu2_add(xa2[p + 16], nt);
                xa2[p]      = mul2(t0, t0);
                xa2[p + 16] = mul2(t1, t1);
                ffma2(s0, t0, t0);
                ffma2(s1, t1, t1);
            }
            float rs = 1.f / hsum2(add2(s0, s1));
            ull rs2 = dup2(rs);
            #pragma unroll
            for (int p = 0; p < 32; p++) xa2[p] = mul2(xa2[p], rs2);
        }
    } else {
        float xs[64];
        #pragma unroll
        for (int p = 0; p < 32; p++) { xs[2 * p] = lo2(xa2[p]); xs[2 * p + 1] = hi2(xa2[p]); }
        float tau_lo = mx - 1.f;
        float dm     = 1.f - exp2f(-6.f * am1);
        float tau_m  = tau_lo;
        float f_lo = -1.f;
        #pragma unroll
        for (int j = 0; j < 64; j++) {
            float z = xs[j] - tau_lo;
            f_lo += (z > 0.f) ? powf(fmaxf(z, 1e-30f), inv) : 0.f;
        }
        for (int it = 0; it < NITER; it++) {
            dm *= 0.5f;
            tau_m = tau_lo + dm;
            float fm = -1.f;
            #pragma unroll
            for (int j = 0; j < 64; j++) {
                float z = xs[j] - tau_m;
                fm += (z > 0.f) ? powf(fmaxf(z, 1e-30f), inv) : 0.f;
            }
            if (fm * f_lo >= 0.f) tau_lo = tau_m;
        }
        float s = 0.f;
        #pragma unroll
        for (int j = 0; j < 64; j++) {
            float z = xs[j] - tau_m;
            float p = (z > 0.f) ? powf(fmaxf(z, 1e-30f), inv) : 0.f;
            xs[j] = p;
            s += p;
        }
        float rs = 1.f / s;
        #pragma unroll
        for (int p = 0; p < 32; p++) xa2[p] = pack2(xs[2 * p] * rs, xs[2 * p + 1] * rs);
    }

    // res[h][i] = sum_j att[i][j] * v[h][j]  -> bf16 hi/lo
    #pragma unroll
    for (int h = 0; h < NH; h++) {
        const float4* vrow = (const float4*)&kv[lt][512 + h * 64];
        ull c0 = 0ULL, c1 = 0ULL;
        #pragma unroll
        for (int j4 = 0; j4 < 8; j4++) {
            float4 v0 = vrow[j4];
            float4 v1 = vrow[j4 + 8];
            ffma2(c0, xa2[j4 * 2 + 0],      pack2(v0.x, v0.y));
            ffma2(c0, xa2[j4 * 2 + 1],      pack2(v0.z, v0.w));
            ffma2(c1, xa2[16 + j4 * 2 + 0], pack2(v1.x, v1.y));
            ffma2(c1, xa2[16 + j4 * 2 + 1], pack2(v1.z, v1.w));
        }
        float r = hsum2(add2(c0, c1));
        __nv_bfloat16 hb = __float2bfloat16(r);
        __nv_bfloat16 lb = __float2bfloat16(r - __bfloat162float(hb));
        size_t o = (size_t)token * HE + h * 64 + i;
        g_res_hi[o] = hb;
        g_res_lo[o] = lb;
    }
}

// ---------------------------------------------------------------------------
// K3 (mma.sync bf16 split): output projection.
// CTA = 64 tokens x 64 outputs, K=512 in 8 chunks of 64.
// Warp grid 4(M) x 2(N): 1 mt x 4 nt. res already bf16 hi/lo (direct copy).
// ---------------------------------------------------------------------------
__global__ __launch_bounds__(256) void k_out(
    const float* __restrict__ Wu, const float* __restrict__ bu,
    float* __restrict__ out)
{
    __shared__ __align__(16) __nv_bfloat16 sA[2][64 * 64];   // 16 KB
    __shared__ __align__(16) __nv_bfloat16 sB[2][64 * 64];   // 16 KB
    const int tid  = threadIdx.x;
    const int tok0 = blockIdx.x * 64;

    const int wid   = tid >> 5, lane = tid & 31;
    const int warpM = wid >> 1, warpN = wid & 1;

    float acc[4][4];
    #pragma unroll
    for (int n = 0; n < 4; n++)
        #pragma unroll
        for (int k = 0; k < 4; k++) acc[n][k] = 0.f;

    const uint32_t aB[2] = { smem_u32(sA[0]), smem_u32(sA[1]) };
    const uint32_t bB[2] = { smem_u32(sB[0]), smem_u32(sB[1]) };
    const int pa[3] = {0, 1, 0}, pb[3] = {0, 0, 1};

    const int arow0 = warpM * 16 + (lane & 15);
    const int brow0 = warpN * 32 + (lane & 15);
    const int chi   = lane >> 4;

    for (int kc = 0; kc < 8; kc++) {
        __syncthreads();
        // A chunk: res bf16 hi/lo, 64 rows x 8 chunks — direct 16B copies
        for (int idx = tid; idx < 512; idx += 256) {
            int row = idx >> 3, c = idx & 7;
            size_t so = (size_t)(tok0 + row) * HE + kc * 64 + c * 8;
            int off = row * 8 + (c ^ (row & 7));
            ((uint4*)sA[0])[off] = *(const uint4*)(g_res_hi + so);
            ((uint4*)sA[1])[off] = *(const uint4*)(g_res_lo + so);
        }
        // B chunk: Wu fp32 -> bf16 hi/lo, 64 rows x 8 chunks
        for (int idx = tid; idx < 512; idx += 256) {
            int row = idx >> 3, c = idx & 7;
            const float* src = Wu + (size_t)row * HE + kc * 64 + c * 8;
            float4 v0 = *(const float4*)src;
            float4 v1 = *(const float4*)(src + 4);
            uint4 hh, ll;
            split2(v0.x, v0.y, hh.x, ll.x);
            split2(v0.z, v0.w, hh.y, ll.y);
            split2(v1.x, v1.y, hh.z, ll.z);
            split2(v1.z, v1.w, hh.w, ll.w);
            int off = row * 8 + (c ^ (row & 7));
            ((uint4*)sB[0])[off] = hh;
            ((uint4*)sB[1])[off] = ll;
        }
        __syncthreads();

        #pragma unroll
        for (int p = 0; p < 3; p++) {
            uint32_t ab = aB[pa[p]], bb = bB[pb[p]];
            #pragma unroll
            for (int kk = 0; kk < 4; kk++) {
                int cc = kk * 2 + chi;
                uint32_t a0, a1, a2, a3;
                { int r = arow0; ldsm4(a0, a1, a2, a3, ab + ((r * 8 + (cc ^ (r & 7))) << 4)); }
                uint32_t b0, b1, b2, b3, b4, b5, b6, b7;
                { int r = brow0;      ldsm4(b0, b1, b2, b3, bb + ((r * 8 + (cc ^ (r & 7))) << 4)); }
                { int r = brow0 + 16; ldsm4(b4, b5, b6, b7, bb + ((r * 8 + (cc ^ (r & 7))) << 4)); }
                mma16816(acc[0], a0, a1, a2, a3, b0, b2);
                mma16816(acc[1], a0, a1, a2, a3, b1, b3);
                mma16816(acc[2], a0, a1, a2, a3, b4, b6);
                mma16816(acc[3], a0, a1, a2, a3, b5, b7);
            }
        }
    }

    const int rbase = tok0 + warpM * 16 + (lane >> 2);
    const int cbase = warpN * 32 + (lane & 3) * 2;
    #pragma unroll
    for (int nt = 0; nt < 4; nt++) {
        int col = cbase + nt * 8;
        float bv0 = __ldg(&bu[col]);
        float bv1 = __ldg(&bu[col + 1]);
        float2 e0 = make_float2(acc[nt][0] + bv0, acc[nt][1] + bv1);
        float2 e1 = make_float2(acc[nt][2] + bv0, acc[nt][3] + bv1);
        *(float2*)(out + (size_t)rbase * 64 + col)       = e0;
        *(float2*)(out + (size_t)(rbase + 8) * 64 + col) = e1;
    }
}

// ---------------------------------------------------------------------------
extern "C" void kernel_launch(void* const* d_in, const int* in_sizes, int n_in,
                              void* d_out, int out_size)
{
    const float* x     = (const float*)d_in[0];
    const float* alpha = (const float*)d_in[1];
    const float* Wk    = (const float*)d_in[2];
    const float* bk    = (const float*)d_in[3];
    const float* Wq    = (const float*)d_in[4];
    const float* bq    = (const float*)d_in[5];
    const float* Wv    = (const float*)d_in[6];
    const float* bv    = (const float*)d_in[7];
    const float* Wu    = (const float*)d_in[8];
    const float* bu    = (const float*)d_in[9];
    float* out = (float*)d_out;

    k_qkv<<<dim3(128, 24), 256>>>(x, Wq, bq, Wk, bk, Wv, bv, alpha);
    k_attn<<<NTOK / 4, 256>>>(alpha);
    k_out<<<NTOK / 64, 256>>>(Wu, bu, out);
}

// round 10
// speedup vs baseline: 1.4663x; 1.0335x over previous
#include <cuda_runtime.h>
#include <cuda_bf16.h>
#include <math.h>
#include <stdint.h>

#define NTOK   16384
#define NH     8
#define HE     512
#define QKVDIM 1536
#define NEWTON 4
#define NITER  16

typedef unsigned long long ull;

// Scratch (static device memory — allocation-free)
__device__ float         g_qkv[NTOK * QKVDIM];  // q (pre-scaled) | k | v
__device__ __nv_bfloat16 g_res_hi[NTOK * HE];
__device__ __nv_bfloat16 g_res_lo[NTOK * HE];
// Pre-split bf16 hi/lo operands (filled once by k_prep)
__device__ __nv_bfloat16 g_xh[NTOK * 64],  g_xl[NTOK * 64];
__device__ __nv_bfloat16 g_wh[1536 * 64],  g_wl[1536 * 64];   // [Wq;Wk;Wv]
__device__ __nv_bfloat16 g_wuh[64 * 512],  g_wul[64 * 512];

// ======================= helpers ===========================================
__device__ __forceinline__ uint32_t smem_u32(const void* p) {
    uint32_t a;
    asm("{ .reg .u64 t; cvta.to.shared.u64 t, %1; cvt.u32.u64 %0, t; }" : "=r"(a) : "l"(p));
    return a;
}
__device__ __forceinline__ void ldsm4(uint32_t& r0, uint32_t& r1, uint32_t& r2, uint32_t& r3,
                                      uint32_t a) {
    asm volatile("ldmatrix.sync.aligned.m8n8.x4.shared.b16 {%0,%1,%2,%3}, [%4];"
                 : "=r"(r0), "=r"(r1), "=r"(r2), "=r"(r3) : "r"(a));
}
__device__ __forceinline__ void mma16816(float* d, uint32_t a0, uint32_t a1, uint32_t a2,
                                         uint32_t a3, uint32_t b0, uint32_t b1) {
    asm volatile(
        "mma.sync.aligned.m16n8k16.row.col.f32.bf16.bf16.f32 "
        "{%0,%1,%2,%3}, {%4,%5,%6,%7}, {%8,%9}, {%0,%1,%2,%3};"
        : "+f"(d[0]), "+f"(d[1]), "+f"(d[2]), "+f"(d[3])
        : "r"(a0), "r"(a1), "r"(a2), "r"(a3), "r"(b0), "r"(b1));
}
__device__ __forceinline__ void split2(float a, float b, uint32_t& hp, uint32_t& lp) {
    __nv_bfloat162 h = __floats2bfloat162_rn(a, b);
    float2 hf = __bfloat1622float2(h);
    __nv_bfloat162 l = __floats2bfloat162_rn(a - hf.x, b - hf.y);
    hp = *reinterpret_cast<uint32_t*>(&h);
    lp = *reinterpret_cast<uint32_t*>(&l);
}

// ---------------- f32x2 packed-math helpers (k_attn) -----------------------
__device__ __forceinline__ ull pack2(float lo, float hi) {
    ull r; asm("mov.b64 %0, {%1, %2};" : "=l"(r) : "f"(lo), "f"(hi)); return r;
}
__device__ __forceinline__ ull dup2(float v) { return pack2(v, v); }
__device__ __forceinline__ float lo2(ull v) {
    float f; asm("{ .reg .b32 hi; mov.b64 {%0, hi}, %1; }" : "=f"(f) : "l"(v)); return f;
}
__device__ __forceinline__ float hi2(ull v) {
    float f; asm("{ .reg .b32 lo; mov.b64 {lo, %0}, %1; }" : "=f"(f) : "l"(v)); return f;
}
__device__ __forceinline__ void ffma2(ull& d, ull a, ull b) {
    asm("fma.rn.f32x2 %0, %1, %2, %0;" : "+l"(d) : "l"(a), "l"(b));
}
__device__ __forceinline__ ull add2(ull a, ull b) {
    ull r; asm("add.rn.f32x2 %0, %1, %2;" : "=l"(r) : "l"(a), "l"(b)); return r;
}
__device__ __forceinline__ ull mul2(ull a, ull b) {
    ull r; asm("mul.rn.f32x2 %0, %1, %2;" : "=l"(r) : "l"(a), "l"(b)); return r;
}
__device__ __forceinline__ float hsum2(ull v) { return lo2(v) + hi2(v); }
__device__ __forceinline__ ull relu2_add(ull x2, ull nt2) {
    ull r;
    asm("{\n\t"
        ".reg .f32 lo, hi;\n\t"
        "add.rn.f32x2 %0, %1, %2;\n\t"
        "mov.b64 {lo, hi}, %0;\n\t"
        "max.f32 lo, lo, 0f00000000;\n\t"
        "max.f32 hi, hi, 0f00000000;\n\t"
        "mov.b64 %0, {lo, hi};\n\t"
        "}" : "=l"(r) : "l"(x2), "l"(nt2));
    return r;
}

// ---------------------------------------------------------------------------
// K0: one-time bf16 hi/lo split of x, [Wq;Wk;Wv], Wu. One float2 per thread.
// ---------------------------------------------------------------------------
#define NXP  (NTOK * 64 / 2)       // 524288 x pairs
#define NWP  (1536 * 64 / 2)       // 49152 w pairs
#define NUP  (64 * 512 / 2)        // 16384 wu pairs
__global__ __launch_bounds__(256) void k_prep(
    const float* __restrict__ x,
    const float* __restrict__ Wq, const float* __restrict__ Wk,
    const float* __restrict__ Wv, const float* __restrict__ Wu)
{
    int idx = blockIdx.x * 256 + threadIdx.x;
    const float* src; __nv_bfloat16* dh; __nv_bfloat16* dl; int p;
    if (idx < NXP)                  { src = x;  dh = g_xh;  dl = g_xl;  p = idx; }
    else if (idx < NXP + NWP) {
        p = idx - NXP;
        int f = p * 2;
        if (f < 32768)      { src = Wq; dh = g_wh; dl = g_wl; }
        else if (f < 65536) { src = Wk - 32768; dh = g_wh; dl = g_wl; }
        else                { src = Wv - 65536; dh = g_wh; dl = g_wl; }
    }
    else if (idx < NXP + NWP + NUP) { p = idx - NXP - NWP; src = Wu; dh = g_wuh; dl = g_wul; }
    else return;
    float2 v = *(const float2*)(src + (size_t)p * 2);
    uint32_t hp, lp;
    split2(v.x, v.y, hp, lp);
    ((uint32_t*)dh)[p] = hp;
    ((uint32_t*)dl)[p] = lp;
}

// ---------------------------------------------------------------------------
// K1 (mma.sync bf16 split): QKV projection, pre-split operands.
// CTA = 128 tokens x 64 outputs. 3 passes: Ah*Bh + Al*Bh + Ah*Bl.
// ---------------------------------------------------------------------------
__global__ __launch_bounds__(256) void k_qkv(
    const float* __restrict__ bq, const float* __restrict__ bk,
    const float* __restrict__ bv, const float* __restrict__ alpha_p)
{
    __shared__ __align__(16) __nv_bfloat16 sA[2][128 * 64];  // 32 KB
    __shared__ __align__(16) __nv_bfloat16 sB[2][64 * 64];   // 16 KB
    const int tid  = threadIdx.x;
    const int bm   = blockIdx.x;
    const int tn   = blockIdx.y;            // 0..23
    const int oBase = tn * 64;

    const float* bias;
    if (tn < 8)       bias = bq;
    else if (tn < 16) bias = bk;
    else              bias = bv;
    const int wBase = oBase & 511;

    // ---- A: 128 rows x 8 x 16B copies, swizzled ----
    for (int idx = tid; idx < 1024; idx += 256) {
        int row = idx >> 3, c = idx & 7;
        size_t so = (size_t)(bm * 128 + row) * 64 + c * 8;
        int off = row * 8 + (c ^ (row & 7));
        ((uint4*)sA[0])[off] = *(const uint4*)(g_xh + so);
        ((uint4*)sA[1])[off] = *(const uint4*)(g_xl + so);
    }
    // ---- B: 64 rows x 8 x 16B copies ----
    for (int idx = tid; idx < 512; idx += 256) {
        int row = idx >> 3, c = idx & 7;
        size_t so = (size_t)(tn * 64 + row) * 64 + c * 8;
        int off = row * 8 + (c ^ (row & 7));
        ((uint4*)sB[0])[off] = *(const uint4*)(g_wh + so);
        ((uint4*)sB[1])[off] = *(const uint4*)(g_wl + so);
    }
    __syncthreads();

    const int wid   = tid >> 5, lane = tid & 31;
    const int warpM = wid >> 1, warpN = wid & 1;

    float acc[2][4][4];
    #pragma unroll
    for (int m = 0; m < 2; m++)
        #pragma unroll
        for (int n = 0; n < 4; n++)
            #pragma unroll
            for (int k = 0; k < 4; k++) acc[m][n][k] = 0.f;

    const uint32_t aB[2] = { smem_u32(sA[0]), smem_u32(sA[1]) };
    const uint32_t bB[2] = { smem_u32(sB[0]), smem_u32(sB[1]) };
    const int pa[3] = {0, 1, 0}, pb[3] = {0, 0, 1};

    const int arow0 = warpM * 32 + (lane & 15);
    const int brow0 = warpN * 32 + (lane & 15);
    const int chi   = lane >> 4;

    // hoisted swizzle offsets (byte offsets); +16 rows = +2048 B
    uint32_t offA[4], offB[4];
    #pragma unroll
    for (int kk = 0; kk < 4; kk++) {
        int cc = kk * 2 + chi;
        offA[kk] = (uint32_t)((arow0 * 8 + (cc ^ (arow0 & 7))) << 4);
        offB[kk] = (uint32_t)((brow0 * 8 + (cc ^ (brow0 & 7))) << 4);
    }

    #pragma unroll
    for (int p = 0; p < 3; p++) {
        uint32_t ab = aB[pa[p]], bb = bB[pb[p]];
        #pragma unroll
        for (int kk = 0; kk < 4; kk++) {
            uint32_t a0, a1, a2, a3, a4, a5, a6, a7;
            ldsm4(a0, a1, a2, a3, ab + offA[kk]);
            ldsm4(a4, a5, a6, a7, ab + offA[kk] + 2048);
            uint32_t b0, b1, b2, b3, b4, b5, b6, b7;
            ldsm4(b0, b1, b2, b3, bb + offB[kk]);
            ldsm4(b4, b5, b6, b7, bb + offB[kk] + 2048);
            mma16816(acc[0][0], a0, a1, a2, a3, b0, b2);
            mma16816(acc[0][1], a0, a1, a2, a3, b1, b3);
            mma16816(acc[0][2], a0, a1, a2, a3, b4, b6);
            mma16816(acc[0][3], a0, a1, a2, a3, b5, b7);
            mma16816(acc[1][0], a4, a5, a6, a7, b0, b2);
            mma16816(acc[1][1], a4, a5, a6, a7, b1, b3);
            mma16816(acc[1][2], a4, a5, a6, a7, b4, b6);
            mma16816(acc[1][3], a4, a5, a6, a7, b5, b7);
        }
    }

    const float am1   = __ldg(alpha_p) - 1.f;
    const float scale = (tn < 8) ? am1 * 0.125f : 1.f;
    const int rbase = bm * 128 + warpM * 32 + (lane >> 2);
    const int cbase = warpN * 32 + (lane & 3) * 2;
    #pragma unroll
    for (int mt = 0; mt < 2; mt++)
        #pragma unroll
        for (int nt = 0; nt < 4; nt++) {
            int col = cbase + nt * 8;
            float bv0 = __ldg(&bias[wBase + col]);
            float bv1 = __ldg(&bias[wBase + col + 1]);
            int row0 = rbase + mt * 16;
            float2 e0 = make_float2((acc[mt][nt][0] + bv0) * scale,
                                    (acc[mt][nt][1] + bv1) * scale);
            float2 e1 = make_float2((acc[mt][nt][2] + bv0) * scale,
                                    (acc[mt][nt][3] + bv1) * scale);
            *(float2*)(g_qkv + (size_t)row0 * QKVDIM + oBase + col)       = e0;
            *(float2*)(g_qkv + (size_t)(row0 + 8) * QKVDIM + oBase + col) = e1;
        }
}

// ---------------------------------------------------------------------------
// K2: scores + entmax (4 Newton + exact-support quadratic solve) + att@V^T.
// ---------------------------------------------------------------------------
__global__ __launch_bounds__(256) void k_attn(const float* __restrict__ alpha_p)
{
    __shared__ float kv[4][1024];
    const int tid   = threadIdx.x;
    const int tok0  = blockIdx.x * 4;
    const int lt    = tid >> 6;
    const int i     = tid & 63;
    const int token = tok0 + lt;

    {
        int f = tid;
        #pragma unroll
        for (int rep = 0; rep < 4; rep++, f += 256) {
            int t    = f >> 8;
            int idx4 = f & 255;
            float4 v = *(const float4*)(g_qkv + (size_t)(tok0 + t) * QKVDIM + 512 + idx4 * 4);
            *(float4*)(&kv[t][idx4 * 4]) = v;
        }
    }
    float q[NH];
    #pragma unroll
    for (int h = 0; h < NH; h++)
        q[h] = g_qkv[(size_t)token * QKVDIM + h * 64 + i];
    __syncthreads();

    const float am1 = alpha_p[0] - 1.f;
    const float inv = 1.f / am1;
    const bool fast = fabsf(inv - 2.f) < 1e-4f;

    ull xa2[32];
    #pragma unroll
    for (int p = 0; p < 32; p++) xa2[p] = 0ULL;
    #pragma unroll
    for (int h = 0; h < NH; h++) {
        ull q2 = dup2(q[h]);
        const float4* krow = (const float4*)&kv[lt][h * 64];
        #pragma unroll
        for (int j4 = 0; j4 < 16; j4++) {
            float4 kk = krow[j4];
            ffma2(xa2[j4 * 2 + 0], q2, pack2(kk.x, kk.y));
            ffma2(xa2[j4 * 2 + 1], q2, pack2(kk.z, kk.w));
        }
    }

    float mx = -3.4e38f;
    #pragma unroll
    for (int p = 0; p < 32; p++)
        mx = fmaxf(mx, fmaxf(lo2(xa2[p]), hi2(xa2[p])));

    float tau = mx - 1.f;

    if (fast) {
        // -------- 4 Newton iterations (monotone from below) --------
        for (int it = 0; it < NEWTON; it++) {
            ull nt = dup2(-tau);
            ull s2a = 0ULL, s2b = 0ULL, s2c = 0ULL, s2d = 0ULL;
            ull s1a = 0ULL, s1b = 0ULL, s1c = 0ULL, s1d = 0ULL;
            #pragma unroll
            for (int j = 0; j < 8; j++) {
                ull t;
                t = relu2_add(xa2[j],      nt); ffma2(s2a, t, t); s1a = add2(s1a, t);
                t = relu2_add(xa2[j +  8], nt); ffma2(s2b, t, t); s1b = add2(s1b, t);
                t = relu2_add(xa2[j + 16], nt); ffma2(s2c, t, t); s1c = add2(s1c, t);
                t = relu2_add(xa2[j + 24], nt); ffma2(s2d, t, t); s1d = add2(s1d, t);
            }
            float f  = hsum2(add2(add2(s2a, s2b), add2(s2c, s2d))) - 1.f;
            float s1 = hsum2(add2(add2(s1a, s1b), add2(s1c, s1d)));
            s1 = fmaxf(s1, 1e-20f);
            tau += __fdividef(f, 2.f * s1);
        }
        // -------- exact-support quadratic solve --------
        // On support S (|S|=k): k*d^2 - 2*s1*d + (s2-1) = 0; from below the
        // fixed-support root d = f/(s1+sqrt(s1^2-k*f)) undershoots or is exact.
        {
            ull nt  = dup2(-tau);
            ull big = dup2(1e30f);
            ull s2a = 0ULL, s2b = 0ULL;
            ull s1a = 0ULL, s1b = 0ULL;
            float ca = 0.f, cb = 0.f;
            #pragma unroll
            for (int j = 0; j < 16; j++) {
                ull t0 = relu2_add(xa2[j],      nt);
                ull t1 = relu2_add(xa2[j + 16], nt);
                ffma2(s2a, t0, t0); s1a = add2(s1a, t0);
                ffma2(s2b, t1, t1); s1b = add2(s1b, t1);
                ull u0 = mul2(t0, big);
                ull u1 = mul2(t1, big);
                ca += fminf(lo2(u0), 1.f) + fminf(hi2(u0), 1.f);
                cb += fminf(lo2(u1), 1.f) + fminf(hi2(u1), 1.f);
            }
            float f  = hsum2(add2(s2a, s2b)) - 1.f;
            float s1 = fmaxf(hsum2(add2(s1a, s1b)), 1e-20f);
            float k  = ca + cb;
            float disc = fmaxf(fmaf(-k, f, s1 * s1), 0.f);
            tau += f / (s1 + sqrtf(disc));
        }
        // -------- p = relu(xa - tau)^2, normalize --------
        {
            ull nt = dup2(-tau);
            ull s0 = 0ULL, s1 = 0ULL;
            #pragma unroll
            for (int p = 0; p < 16; p++) {
                ull t0 = relu2_add(xa2[p],      nt);
                ull t1 = relu2_add(xa2[p + 16], nt);
                xa2[p]      = mul2(t0, t0);
                xa2[p + 16] = mul2(t1, t1);
                ffma2(s0, t0, t0);
                ffma2(s1, t1, t1);
            }
            float rs = 1.f / hsum2(add2(s0, s1));
            ull rs2 = dup2(rs);
            #pragma unroll
            for (int p = 0; p < 32; p++) xa2[p] = mul2(xa2[p], rs2);
        }
    } else {
        float xs[64];
        #pragma unroll
        for (int p = 0; p < 32; p++) { xs[2 * p] = lo2(xa2[p]); xs[2 * p + 1] = hi2(xa2[p]); }
        float tau_lo = mx - 1.f;
        float dm     = 1.f - exp2f(-6.f * am1);
        float tau_m  = tau_lo;
        float f_lo = -1.f;
        #pragma unroll
        for (int j = 0; j < 64; j++) {
            float z = xs[j] - tau_lo;
            f_lo += (z > 0.f) ? powf(fmaxf(z, 1e-30f), inv) : 0.f;
        }
        for (int it = 0; it < NITER; it++) {
            dm *= 0.5f;
            tau_m = tau_lo + dm;
            float fm = -1.f;
            #pragma unroll
            for (int j = 0; j < 64; j++) {
                float z = xs[j] - tau_m;
                fm += (z > 0.f) ? powf(fmaxf(z, 1e-30f), inv) : 0.f;
            }
            if (fm * f_lo >= 0.f) tau_lo = tau_m;
        }
        float s = 0.f;
        #pragma unroll
        for (int j = 0; j < 64; j++) {
            float z = xs[j] - tau_m;
            float p = (z > 0.f) ? powf(fmaxf(z, 1e-30f), inv) : 0.f;
            xs[j] = p;
            s += p;
        }
        float rs = 1.f / s;
        #pragma unroll
        for (int p = 0; p < 32; p++) xa2[p] = pack2(xs[2 * p] * rs, xs[2 * p + 1] * rs);
    }

    // res[h][i] = sum_j att[i][j] * v[h][j]  -> bf16 hi/lo
    #pragma unroll
    for (int h = 0; h < NH; h++) {
        const float4* vrow = (const float4*)&kv[lt][512 + h * 64];
        ull c0 = 0ULL, c1 = 0ULL;
        #pragma unroll
        for (int j4 = 0; j4 < 8; j4++) {
            float4 v0 = vrow[j4];
            float4 v1 = vrow[j4 + 8];
            ffma2(c0, xa2[j4 * 2 + 0],      pack2(v0.x, v0.y));
            ffma2(c0, xa2[j4 * 2 + 1],      pack2(v0.z, v0.w));
            ffma2(c1, xa2[16 + j4 * 2 + 0], pack2(v1.x, v1.y));
            ffma2(c1, xa2[16 + j4 * 2 + 1], pack2(v1.z, v1.w));
        }
        float r = hsum2(add2(c0, c1));
        __nv_bfloat16 hb = __float2bfloat16(r);
        __nv_bfloat16 lb = __float2bfloat16(r - __bfloat162float(hb));
        size_t o = (size_t)token * HE + h * 64 + i;
        g_res_hi[o] = hb;
        g_res_lo[o] = lb;
    }
}

// ---------------------------------------------------------------------------
// K3 (mma.sync bf16 split): output projection, pre-split Wu.
// CTA = 64 tokens x 64 outputs, K=512 in 8 chunks of 64.
// ---------------------------------------------------------------------------
__global__ __launch_bounds__(256) void k_out(
    const float* __restrict__ bu, float* __restrict__ out)
{
    __shared__ __align__(16) __nv_bfloat16 sA[2][64 * 64];
    __shared__ __align__(16) __nv_bfloat16 sB[2][64 * 64];
    const int tid  = threadIdx.x;
    const int tok0 = blockIdx.x * 64;

    const int wid   = tid >> 5, lane = tid & 31;
    const int warpM = wid >> 1, warpN = wid & 1;

    float acc[4][4];
    #pragma unroll
    for (int n = 0; n < 4; n++)
        #pragma unroll
        for (int k = 0; k < 4; k++) acc[n][k] = 0.f;

    const uint32_t aB[2] = { smem_u32(sA[0]), smem_u32(sA[1]) };
    const uint32_t bB[2] = { smem_u32(sB[0]), smem_u32(sB[1]) };
    const int pa[3] = {0, 1, 0}, pb[3] = {0, 0, 1};

    const int arow0 = warpM * 16 + (lane & 15);
    const int brow0 = warpN * 32 + (lane & 15);
    const int chi   = lane >> 4;

    uint32_t offA[4], offB[4];
    #pragma unroll
    for (int kk = 0; kk < 4; kk++) {
        int cc = kk * 2 + chi;
        offA[kk] = (uint32_t)((arow0 * 8 + (cc ^ (arow0 & 7))) << 4);
        offB[kk] = (uint32_t)((brow0 * 8 + (cc ^ (brow0 & 7))) << 4);
    }

    for (int kc = 0; kc < 8; kc++) {
        __syncthreads();
        for (int idx = tid; idx < 512; idx += 256) {
            int row = idx >> 3, c = idx & 7;
            size_t so = (size_t)(tok0 + row) * HE + kc * 64 + c * 8;
            int off = row * 8 + (c ^ (row & 7));
            ((uint4*)sA[0])[off] = *(const uint4*)(g_res_hi + so);
            ((uint4*)sA[1])[off] = *(const uint4*)(g_res_lo + so);
        }
        for (int idx = tid; idx < 512; idx += 256) {
            int row = idx >> 3, c = idx & 7;
            size_t so = (size_t)row * HE + kc * 64 + c * 8;
            int off = row * 8 + (c ^ (row & 7));
            ((uint4*)sB[0])[off] = *(const uint4*)(g_wuh + so);
            ((uint4*)sB[1])[off] = *(const uint4*)(g_wul + so);
        }
        __syncthreads();

        #pragma unroll
        for (int p = 0; p < 3; p++) {
            uint32_t ab = aB[pa[p]], bb = bB[pb[p]];
            #pragma unroll
            for (int kk = 0; kk < 4; kk++) {
                uint32_t a0, a1, a2, a3;
                ldsm4(a0, a1, a2, a3, ab + offA[kk]);
                uint32_t b0, b1, b2, b3, b4, b5, b6, b7;
                ldsm4(b0, b1, b2, b3, bb + offB[kk]);
                ldsm4(b4, b5, b6, b7, bb + offB[kk] + 2048);
                mma16816(acc[0], a0, a1, a2, a3, b0, b2);
                mma16816(acc[1], a0, a1, a2, a3, b1, b3);
                mma16816(acc[2], a0, a1, a2, a3, b4, b6);
                mma16816(acc[3], a0, a1, a2, a3, b5, b7);
            }
        }
    }

    const int rbase = tok0 + warpM * 16 + (lane >> 2);
    const int cbase = warpN * 32 + (lane & 3) * 2;
    #pragma unroll
    for (int nt = 0; nt < 4; nt++) {
        int col = cbase + nt * 8;
        float bv0 = __ldg(&bu[col]);
        float bv1 = __ldg(&bu[col + 1]);
        float2 e0 = make_float2(acc[nt][0] + bv0, acc[nt][1] + bv1);
        float2 e1 = make_float2(acc[nt][2] + bv0, acc[nt][3] + bv1);
        *(float2*)(out + (size_t)rbase * 64 + col)       = e0;
        *(float2*)(out + (size_t)(rbase + 8) * 64 + col) = e1;
    }
}

// ---------------------------------------------------------------------------
extern "C" void kernel_launch(void* const* d_in, const int* in_sizes, int n_in,
                              void* d_out, int out_size)
{
    const float* x     = (const float*)d_in[0];
    const float* alpha = (const float*)d_in[1];
    const float* Wk    = (const float*)d_in[2];
    const float* bk    = (const float*)d_in[3];
    const float* Wq    = (const float*)d_in[4];
    const float* bq    = (const float*)d_in[5];
    const float* Wv    = (const float*)d_in[6];
    const float* bv    = (const float*)d_in[7];
    const float* Wu    = (const float*)d_in[8];
    const float* bu    = (const float*)d_in[9];
    float* out = (float*)d_out;

    int prep_blocks = (NXP + NWP + NUP + 255) / 256;
    k_prep<<<prep_blocks, 256>>>(x, Wq, Wk, Wv, Wu);
    k_qkv<<<dim3(128, 24), 256>>>(bq, bk, bv, alpha);
    k_attn<<<NTOK / 4, 256>>>(alpha);
    k_out<<<NTOK / 64, 256>>>(bu, out);
}